// round 1
// baseline (speedup 1.0000x reference)
#include <cuda_runtime.h>
#include <math.h>

#define Bb 64
#define Nn 512
#define Dd 256
#define Ll 4

// ---------------- scratch ----------------
__device__ float g_x [Bb * Nn * Dd];   // current x
__device__ float g_q [Bb * Nn * Dd];   // q, then reused as lin0 output
__device__ float g_t1[Bb * Nn * Dd];   // attn @ x

// ---------------- copy kernel ----------------
__global__ void copy_f4(const float4* __restrict__ src, float4* __restrict__ dst, int n4) {
    int i = blockIdx.x * blockDim.x + threadIdx.x;
    if (i < n4) dst[i] = src[i];
}

// ---------------- GEMM NT: C = A[M,K] @ B[Nc,K]^T ----------------
// EPI: 1 = +bias ; 2 = relu(+bias) ; 3 = relu(+bias)+res ; 4 = attention epilogue
#define BM 64
#define BN 64
#define BK 16

template<int EPI>
__global__ void __launch_bounds__(256)
gemm_nt_kernel(const float* __restrict__ A, const float* __restrict__ B,
               float* __restrict__ C, int M, int Nc, int K,
               size_t sA, size_t sB, size_t sC,
               const float* __restrict__ bias,
               const float* __restrict__ res,
               const float* __restrict__ adj)
{
    const int bz = blockIdx.z;
    A += (size_t)bz * sA;
    B += (size_t)bz * sB;
    C += (size_t)bz * sC;
    const float* adjb = adj + (size_t)bz * Nn * Nn;   // only used if EPI==4

    __shared__ float As[BK][BM];
    __shared__ float Bs[BK][BN];

    const int tid = threadIdx.x;
    const int tx = tid & 15;        // 0..15 -> 4 cols each
    const int ty = tid >> 4;        // 0..15 -> 4 rows each
    const int bm = blockIdx.y * BM;
    const int bn = blockIdx.x * BN;

    // load indices: 256 threads, each loads a float4 from a row
    const int lm  = tid >> 2;       // 0..63 row within tile
    const int lk4 = (tid & 3) * 4;  // 0,4,8,12 col (k) within tile

    float acc[4][4];
    #pragma unroll
    for (int i = 0; i < 4; i++)
        #pragma unroll
        for (int j = 0; j < 4; j++) acc[i][j] = 0.0f;

    for (int k0 = 0; k0 < K; k0 += BK) {
        float4 av = *(const float4*)(A + (size_t)(bm + lm) * K + k0 + lk4);
        float4 bv = *(const float4*)(B + (size_t)(bn + lm) * K + k0 + lk4);
        As[lk4 + 0][lm] = av.x; As[lk4 + 1][lm] = av.y;
        As[lk4 + 2][lm] = av.z; As[lk4 + 3][lm] = av.w;
        Bs[lk4 + 0][lm] = bv.x; Bs[lk4 + 1][lm] = bv.y;
        Bs[lk4 + 2][lm] = bv.z; Bs[lk4 + 3][lm] = bv.w;
        __syncthreads();
        #pragma unroll
        for (int kk = 0; kk < BK; kk++) {
            float4 a4 = *(const float4*)&As[kk][ty * 4];
            float4 b4 = *(const float4*)&Bs[kk][tx * 4];
            float ar[4] = {a4.x, a4.y, a4.z, a4.w};
            float br[4] = {b4.x, b4.y, b4.z, b4.w};
            #pragma unroll
            for (int i = 0; i < 4; i++)
                #pragma unroll
                for (int j = 0; j < 4; j++)
                    acc[i][j] = fmaf(ar[i], br[j], acc[i][j]);
        }
        __syncthreads();
    }

    #pragma unroll
    for (int i = 0; i < 4; i++) {
        const int row = bm + ty * 4 + i;
        #pragma unroll
        for (int j = 0; j < 4; j++) {
            const int col = bn + tx * 4 + j;
            float c = acc[i][j];
            if (EPI == 1) {
                c += bias[col];
            } else if (EPI == 2) {
                c = fmaxf(c + bias[col], 0.0f);
            } else if (EPI == 3) {
                c = fmaxf(c + bias[col], 0.0f) + res[(size_t)row * Nc + col];
            } else if (EPI == 4) {
                float s = 1.0f / (1.0f + expf(-c));
                if (row == col) {
                    c = (s + 1e-5f);            // adj diag forced to 1
                } else {
                    c = s * adjb[(size_t)row * Nn + col];
                }
            }
            C[(size_t)row * Nc + col] = c;
        }
    }
}

// ---------------- GEMM NN: C = A[M,K] @ B[K,Nc] ----------------
__global__ void __launch_bounds__(256)
gemm_nn_kernel(const float* __restrict__ A, const float* __restrict__ B,
               float* __restrict__ C, int M, int Nc, int K,
               size_t sA, size_t sB, size_t sC)
{
    const int bz = blockIdx.z;
    A += (size_t)bz * sA;
    B += (size_t)bz * sB;
    C += (size_t)bz * sC;

    __shared__ float As[BK][BM];
    __shared__ float Bs[BK][BN];

    const int tid = threadIdx.x;
    const int tx = tid & 15;
    const int ty = tid >> 4;
    const int bm = blockIdx.y * BM;
    const int bn = blockIdx.x * BN;

    // A load (transpose into smem): same as NT
    const int lm  = tid >> 2;
    const int lk4 = (tid & 3) * 4;
    // B load (direct): 16 k-rows x 64 cols
    const int lkB = tid >> 4;        // 0..15
    const int ln4 = (tid & 15) * 4;  // 0..60

    float acc[4][4];
    #pragma unroll
    for (int i = 0; i < 4; i++)
        #pragma unroll
        for (int j = 0; j < 4; j++) acc[i][j] = 0.0f;

    for (int k0 = 0; k0 < K; k0 += BK) {
        float4 av = *(const float4*)(A + (size_t)(bm + lm) * K + k0 + lk4);
        As[lk4 + 0][lm] = av.x; As[lk4 + 1][lm] = av.y;
        As[lk4 + 2][lm] = av.z; As[lk4 + 3][lm] = av.w;
        float4 bv = *(const float4*)(B + (size_t)(k0 + lkB) * Nc + bn + ln4);
        *(float4*)&Bs[lkB][ln4] = bv;
        __syncthreads();
        #pragma unroll
        for (int kk = 0; kk < BK; kk++) {
            float4 a4 = *(const float4*)&As[kk][ty * 4];
            float4 b4 = *(const float4*)&Bs[kk][tx * 4];
            float ar[4] = {a4.x, a4.y, a4.z, a4.w};
            float br[4] = {b4.x, b4.y, b4.z, b4.w};
            #pragma unroll
            for (int i = 0; i < 4; i++)
                #pragma unroll
                for (int j = 0; j < 4; j++)
                    acc[i][j] = fmaf(ar[i], br[j], acc[i][j]);
        }
        __syncthreads();
    }

    #pragma unroll
    for (int i = 0; i < 4; i++) {
        const int row = bm + ty * 4 + i;
        #pragma unroll
        for (int j = 0; j < 4; j++) {
            const int col = bn + tx * 4 + j;
            C[(size_t)row * Nc + col] = acc[i][j];
        }
    }
}

// ---------------- row normalize (one block per row of N=512) ----------------
__global__ void __launch_bounds__(256)
rownorm_kernel(float* __restrict__ a)
{
    const size_t row = blockIdx.x;
    float* p = a + row * Nn;
    const int t = threadIdx.x;
    float v0 = p[t];
    float v1 = p[t + 256];
    float s = v0 + v1;
    #pragma unroll
    for (int o = 16; o; o >>= 1) s += __shfl_xor_sync(0xffffffffu, s, o);
    __shared__ float ws[8];
    if ((t & 31) == 0) ws[t >> 5] = s;
    __syncthreads();
    if (t < 8) {
        float x = ws[t];
        #pragma unroll
        for (int o = 4; o; o >>= 1) x += __shfl_xor_sync(0xffu, x, o);
        if (t == 0) ws[0] = x;
    }
    __syncthreads();
    const float inv = 1.0f / ws[0];
    p[t]       = v0 * inv;
    p[t + 256] = v1 * inv;
}

// ---------------- launch ----------------
extern "C" void kernel_launch(void* const* d_in, const int* in_sizes, int n_in,
                              void* d_out, int out_size)
{
    const float* x_in    = (const float*)d_in[0];
    const float* adj     = (const float*)d_in[1];
    const float* wA_w    = (const float*)d_in[2];
    const float* wA_b    = (const float*)d_in[3];
    const float* l0_w    = (const float*)d_in[4];
    const float* l0_b    = (const float*)d_in[5];
    const float* l1_w    = (const float*)d_in[6];
    const float* l1_b    = (const float*)d_in[7];
    const float* fin_w   = (const float*)d_in[8];
    const float* fin_b   = (const float*)d_in[9];

    float* out_x   = (float*)d_out;
    float* attls   = out_x + (size_t)Bb * Nn * Dd;

    float* gx;  cudaGetSymbolAddress((void**)&gx,  g_x);
    float* gq;  cudaGetSymbolAddress((void**)&gq,  g_q);
    float* gt1; cudaGetSymbolAddress((void**)&gt1, g_t1);

    const int   BIGM = Bb * Nn;              // 32768
    const size_t XSZ = (size_t)Bb * Nn * Dd; // 8.4M floats

    // x -> g_x
    {
        int n4 = (int)(XSZ / 4);
        copy_f4<<<(n4 + 255) / 256, 256>>>((const float4*)x_in, (float4*)gx, n4);
    }

    dim3 thr(256);
    for (int l = 0; l < Ll; l++) {
        const float* Wa = wA_w + (size_t)l * Dd * Dd;
        const float* ba = wA_b + (size_t)l * Dd;
        const float* W0 = l0_w + (size_t)l * Dd * Dd;
        const float* b0 = l0_b + (size_t)l * Dd;
        const float* W1 = l1_w + (size_t)l * Dd * Dd;
        const float* b1 = l1_b + (size_t)l * Dd;
        float* attl = attls + (size_t)l * Bb * Nn * Nn;

        // q = x @ Wa^T + ba            [32768,256] x [256,256]
        gemm_nt_kernel<1><<<dim3(Dd / BN, BIGM / BM, 1), thr>>>(
            gx, Wa, gq, BIGM, Dd, Dd, 0, 0, 0, ba, nullptr, nullptr);

        // attn (unnormalized) = sig(q @ x^T) masked, per batch  [512,512] K=256
        gemm_nt_kernel<4><<<dim3(Nn / BN, Nn / BM, Bb), thr>>>(
            gq, gx, attl, Nn, Nn, Dd,
            (size_t)Nn * Dd, (size_t)Nn * Dd, (size_t)Nn * Nn,
            nullptr, nullptr, adj);

        // row normalize in place
        rownorm_kernel<<<Bb * Nn, 256>>>(attl);

        // t1 = attn @ x, per batch     [512,256] K=512
        gemm_nn_kernel<<<dim3(Dd / BN, Nn / BM, Bb), thr>>>(
            attl, gx, gt1, Nn, Dd, Nn,
            (size_t)Nn * Nn, (size_t)Nn * Dd, (size_t)Nn * Dd);

        // h = relu(t1 @ W0^T + b0) -> gq (q dead)
        gemm_nt_kernel<2><<<dim3(Dd / BN, BIGM / BM, 1), thr>>>(
            gt1, W0, gq, BIGM, Dd, Dd, 0, 0, 0, b0, nullptr, nullptr);

        // x = relu(h @ W1^T + b1) + x0 -> gx (read-then-write same index: safe)
        gemm_nt_kernel<3><<<dim3(Dd / BN, BIGM / BM, 1), thr>>>(
            gq, W1, gx, BIGM, Dd, Dd, 0, 0, 0, b1, gx, nullptr);
    }

    // out_x = x @ final_w^T + final_b
    gemm_nt_kernel<1><<<dim3(Dd / BN, BIGM / BM, 1), thr>>>(
        gx, fin_w, out_x, BIGM, Dd, Dd, 0, 0, 0, fin_b, nullptr, nullptr);
}

// round 3
// speedup vs baseline: 2.0036x; 2.0036x over previous
#include <cuda_runtime.h>
#include <cuda_bf16.h>
#include <cstdint>
#include <math.h>

#define Bb 64
#define Nn 512
#define Dd 256
#define Ll 4

// ======================= helpers =======================
__device__ __forceinline__ uint32_t smem_u32(const void* p) {
    uint32_t a;
    asm("{ .reg .u64 t; cvta.to.shared.u64 t, %1; cvt.u32.u64 %0, t; }" : "=r"(a) : "l"(p));
    return a;
}
__device__ __forceinline__ void cp16(uint32_t s, const void* g) {
    asm volatile("cp.async.cg.shared.global [%0], [%1], 16;" :: "r"(s), "l"(g));
}
__device__ __forceinline__ void ldsm4(uint32_t* r, uint32_t addr) {
    asm volatile("ldmatrix.sync.aligned.m8n8.x4.shared.b16 {%0,%1,%2,%3}, [%4];"
        : "=r"(r[0]), "=r"(r[1]), "=r"(r[2]), "=r"(r[3]) : "r"(addr));
}
__device__ __forceinline__ void mma16816(float* d, const uint32_t* a, const uint32_t* b) {
    asm volatile("mma.sync.aligned.m16n8k16.row.col.f32.bf16.bf16.f32 "
        "{%0,%1,%2,%3}, {%4,%5,%6,%7}, {%8,%9}, {%0,%1,%2,%3};"
        : "+f"(d[0]), "+f"(d[1]), "+f"(d[2]), "+f"(d[3])
        : "r"(a[0]), "r"(a[1]), "r"(a[2]), "r"(a[3]), "r"(b[0]), "r"(b[1]));
}

// ======================= device globals (scratch) =======================
#define XSZ (Bb * Nn * Dd)
#define ASZ (Bb * Nn * Nn)
__device__ __align__(128) __nv_bfloat16 g_xh[XSZ], g_xl[XSZ];
__device__ __align__(128) __nv_bfloat16 g_th[XSZ], g_tl[XSZ];   // xT, then lin0 output
__device__ __align__(128) __nv_bfloat16 g_qh[XSZ], g_ql[XSZ];   // q, then t1
__device__ __align__(128) __nv_bfloat16 g_ah[ASZ], g_al[ASZ];   // attn hi/lo
__device__ __align__(128) __nv_bfloat16 g_wh[13 * Dd * Dd], g_wl[13 * Dd * Dd];
__device__ __align__(128) float g_x[XSZ];

// ======================= MMA GEMM (NT, K-major both operands) =======================
// C[M, Ncols] = (Ah+Al)[M,K] @ ((Bh+Bl)[Ncols,K])^T ; fp32 accum via 3 HMMA products.
// EPI: 1=bias->hl | 2=sigmoid*adj fp32 | 3=plain->hl | 4=relu(bias)->hl
//      5=relu(bias)+res -> fp32+hl | 6=bias->fp32
#define TM 128
#define TN 128
#define RS 80                          // padded smem row stride (bytes) for 64B rows
#define MAT_BYTES (128 * RS)           // 10240
#define STAGE_BYTES (4 * MAT_BYTES)    // Ah, Al, Bh, Bl
#define GEMM_SMEM (2 * STAGE_BYTES)    // 81920

template<int EPI>
__global__ void __launch_bounds__(256, 1)
mma_gemm(const __nv_bfloat16* __restrict__ Ah, const __nv_bfloat16* __restrict__ Al,
         const __nv_bfloat16* __restrict__ Bh, const __nv_bfloat16* __restrict__ Bl,
         int K, long long sAz, long long sBz,
         float* __restrict__ Cf, __nv_bfloat16* __restrict__ Ch, __nv_bfloat16* __restrict__ Cl,
         long long sCz, int ldc,
         const float* __restrict__ bias, const float* __restrict__ res,
         const float* __restrict__ adj)
{
    extern __shared__ char smch[];
    const uint32_t sb = smem_u32(smch);
    const int tid = threadIdx.x;
    const int wid = tid >> 5;
    const int lane = tid & 31;
    const int z = blockIdx.z;
    const int bm = blockIdx.x * TM;
    const int bn = blockIdx.y * TN;

    Ah += (size_t)z * sAz + (size_t)bm * K;
    Al += (size_t)z * sAz + (size_t)bm * K;
    Bh += (size_t)z * sBz + (size_t)bn * K;
    Bl += (size_t)z * sBz + (size_t)bn * K;

    // loader geometry: each thread owns one 32B segment of one row, per matrix
    const int lr = tid >> 1;            // row 0..127
    const int lc = (tid & 1) * 2;       // chunk pair 0 or 2
    const uint32_t s_off = (uint32_t)lr * RS + (uint32_t)lc * 16;

    auto issue = [&](int kb, int buf) {
        const size_t go = (size_t)lr * K + (size_t)kb * 32 + (size_t)lc * 8;
        const uint32_t s0 = sb + buf * STAGE_BYTES + s_off;
        cp16(s0,                     Ah + go);
        cp16(s0 + 16,                Ah + go + 8);
        cp16(s0 + MAT_BYTES,         Al + go);
        cp16(s0 + MAT_BYTES + 16,    Al + go + 8);
        cp16(s0 + 2 * MAT_BYTES,      Bh + go);
        cp16(s0 + 2 * MAT_BYTES + 16, Bh + go + 8);
        cp16(s0 + 3 * MAT_BYTES,      Bl + go);
        cp16(s0 + 3 * MAT_BYTES + 16, Bl + go + 8);
    };

    const int KB = K / 32;
    issue(0, 0);
    asm volatile("cp.async.commit_group;" ::: "memory");
    issue(1, 1);
    asm volatile("cp.async.commit_group;" ::: "memory");

    const int wm = (wid & 1) * 64;      // warp row offset in tile
    const int wn = (wid >> 1) * 32;     // warp col offset in tile

    float acc[4][4][4];
    #pragma unroll
    for (int i = 0; i < 4; i++)
        #pragma unroll
        for (int j = 0; j < 4; j++)
            #pragma unroll
            for (int k = 0; k < 4; k++) acc[i][j][k] = 0.0f;

    const int rr = lane & 15;
    const int csel = lane >> 4;         // 0/1 -> second 16B chunk of the k16

    for (int kb = 0; kb < KB; kb++) {
        asm volatile("cp.async.wait_group 1;" ::: "memory");
        __syncthreads();
        const uint32_t bufb = sb + (kb & 1) * STAGE_BYTES;

        #pragma unroll
        for (int ks = 0; ks < 2; ks++) {
            const uint32_t coff = (uint32_t)(ks * 2 + csel) * 16;
            uint32_t ah[4][4], al[4][4], bh[4][2], bl[4][2];
            const uint32_t abase = bufb + (uint32_t)(wm + rr) * RS + coff;
            #pragma unroll
            for (int mt = 0; mt < 4; mt++) {
                ldsm4(ah[mt], abase + mt * (16 * RS));
                ldsm4(al[mt], abase + mt * (16 * RS) + MAT_BYTES);
            }
            const uint32_t bbase = bufb + 2 * MAT_BYTES + (uint32_t)(wn + rr) * RS + coff;
            #pragma unroll
            for (int ntt = 0; ntt < 2; ntt++) {
                uint32_t t4[4];
                ldsm4(t4, bbase + ntt * (16 * RS));
                bh[2 * ntt][0] = t4[0]; bh[2 * ntt][1] = t4[2];
                bh[2 * ntt + 1][0] = t4[1]; bh[2 * ntt + 1][1] = t4[3];
                ldsm4(t4, bbase + ntt * (16 * RS) + MAT_BYTES);
                bl[2 * ntt][0] = t4[0]; bl[2 * ntt][1] = t4[2];
                bl[2 * ntt + 1][0] = t4[1]; bl[2 * ntt + 1][1] = t4[3];
            }
            #pragma unroll
            for (int mt = 0; mt < 4; mt++)
                #pragma unroll
                for (int nt = 0; nt < 4; nt++) {
                    mma16816(acc[mt][nt], ah[mt], bh[nt]);
                    mma16816(acc[mt][nt], ah[mt], bl[nt]);
                    mma16816(acc[mt][nt], al[mt], bh[nt]);
                }
        }
        __syncthreads();
        if (kb + 2 < KB) issue(kb + 2, kb & 1);
        asm volatile("cp.async.commit_group;" ::: "memory");
    }

    // ======================= epilogue =======================
    const int qrow = lane >> 2;         // 0..7
    const int qcol = (lane & 3) * 2;    // 0,2,4,6

    #pragma unroll
    for (int mt = 0; mt < 4; mt++) {
        const int r0 = bm + wm + mt * 16 + qrow;
        const int r1 = r0 + 8;
        #pragma unroll
        for (int nt = 0; nt < 4; nt++) {
            const int col = bn + wn + nt * 8 + qcol;
            float v00 = acc[mt][nt][0], v01 = acc[mt][nt][1];
            float v10 = acc[mt][nt][2], v11 = acc[mt][nt][3];

            if (EPI == 2) {
                float* cf0 = Cf + (size_t)z * sCz + (size_t)r0 * ldc;
                float* cf1 = Cf + (size_t)z * sCz + (size_t)r1 * ldc;
                const float* a0 = adj + ((size_t)z * Nn + r0) * Nn;
                const float* a1 = adj + ((size_t)z * Nn + r1) * Nn;
                float s00 = 1.0f / (1.0f + __expf(-v00));
                float s01 = 1.0f / (1.0f + __expf(-v01));
                float s10 = 1.0f / (1.0f + __expf(-v10));
                float s11 = 1.0f / (1.0f + __expf(-v11));
                cf0[col]     = (col == r0)     ? (s00 + 1e-5f) : s00 * __ldg(a0 + col);
                cf0[col + 1] = (col + 1 == r0) ? (s01 + 1e-5f) : s01 * __ldg(a0 + col + 1);
                cf1[col]     = (col == r1)     ? (s10 + 1e-5f) : s10 * __ldg(a1 + col);
                cf1[col + 1] = (col + 1 == r1) ? (s11 + 1e-5f) : s11 * __ldg(a1 + col + 1);
            } else if (EPI == 6) {
                const float b0v = __ldg(bias + col), b1v = __ldg(bias + col + 1);
                float* cf0 = Cf + (size_t)z * sCz + (size_t)r0 * ldc;
                float* cf1 = Cf + (size_t)z * sCz + (size_t)r1 * ldc;
                float2 p0; p0.x = v00 + b0v; p0.y = v01 + b1v;
                float2 p1; p1.x = v10 + b0v; p1.y = v11 + b1v;
                *(float2*)(cf0 + col) = p0;
                *(float2*)(cf1 + col) = p1;
            } else {
                if (EPI == 1) {
                    const float b0v = __ldg(bias + col), b1v = __ldg(bias + col + 1);
                    v00 += b0v; v01 += b1v; v10 += b0v; v11 += b1v;
                }
                if (EPI == 4 || EPI == 5) {
                    const float b0v = __ldg(bias + col), b1v = __ldg(bias + col + 1);
                    v00 = fmaxf(v00 + b0v, 0.0f); v01 = fmaxf(v01 + b1v, 0.0f);
                    v10 = fmaxf(v10 + b0v, 0.0f); v11 = fmaxf(v11 + b1v, 0.0f);
                }
                if (EPI == 5) {
                    const float* rp0 = res + (size_t)r0 * ldc;
                    const float* rp1 = res + (size_t)r1 * ldc;
                    v00 += rp0[col]; v01 += rp0[col + 1];
                    v10 += rp1[col]; v11 += rp1[col + 1];
                    float* cf0 = Cf + (size_t)r0 * ldc;
                    float* cf1 = Cf + (size_t)r1 * ldc;
                    float2 p0; p0.x = v00; p0.y = v01;
                    float2 p1; p1.x = v10; p1.y = v11;
                    *(float2*)(cf0 + col) = p0;
                    *(float2*)(cf1 + col) = p1;
                }
                __nv_bfloat16* ch0 = Ch + (size_t)z * sCz + (size_t)r0 * ldc;
                __nv_bfloat16* ch1 = Ch + (size_t)z * sCz + (size_t)r1 * ldc;
                __nv_bfloat16* cl0 = Cl + (size_t)z * sCz + (size_t)r0 * ldc;
                __nv_bfloat16* cl1 = Cl + (size_t)z * sCz + (size_t)r1 * ldc;
                __nv_bfloat16 h00 = __float2bfloat16_rn(v00), h01 = __float2bfloat16_rn(v01);
                __nv_bfloat16 h10 = __float2bfloat16_rn(v10), h11 = __float2bfloat16_rn(v11);
                __nv_bfloat162 hp0; hp0.x = h00; hp0.y = h01;
                __nv_bfloat162 hp1; hp1.x = h10; hp1.y = h11;
                *(__nv_bfloat162*)(ch0 + col) = hp0;
                *(__nv_bfloat162*)(ch1 + col) = hp1;
                __nv_bfloat162 lp0, lp1;
                lp0.x = __float2bfloat16_rn(v00 - __bfloat162float(h00));
                lp0.y = __float2bfloat16_rn(v01 - __bfloat162float(h01));
                lp1.x = __float2bfloat16_rn(v10 - __bfloat162float(h10));
                lp1.y = __float2bfloat16_rn(v11 - __bfloat162float(h11));
                *(__nv_bfloat162*)(cl0 + col) = lp0;
                *(__nv_bfloat162*)(cl1 + col) = lp1;
            }
        }
    }
}

// ======================= small kernels =======================
__global__ void __launch_bounds__(256)
split_copy(const float4* __restrict__ src, float4* __restrict__ dst,
           __nv_bfloat16* __restrict__ h, __nv_bfloat16* __restrict__ l, int n4)
{
    const int i = blockIdx.x * blockDim.x + threadIdx.x;
    if (i >= n4) return;
    const float4 v = src[i];
    dst[i] = v;
    const float vv[4] = {v.x, v.y, v.z, v.w};
    __nv_bfloat16 hh[4], ll[4];
    #pragma unroll
    for (int k = 0; k < 4; k++) {
        hh[k] = __float2bfloat16_rn(vv[k]);
        ll[k] = __float2bfloat16_rn(vv[k] - __bfloat162float(hh[k]));
    }
    __nv_bfloat162 a, b;
    a.x = hh[0]; a.y = hh[1]; b.x = hh[2]; b.y = hh[3];
    *(__nv_bfloat162*)(h + 4 * (size_t)i) = a;
    *(__nv_bfloat162*)(h + 4 * (size_t)i + 2) = b;
    a.x = ll[0]; a.y = ll[1]; b.x = ll[2]; b.y = ll[3];
    *(__nv_bfloat162*)(l + 4 * (size_t)i) = a;
    *(__nv_bfloat162*)(l + 4 * (size_t)i + 2) = b;
}

__global__ void __launch_bounds__(256)
wsplit(const float* __restrict__ src, __nv_bfloat16* __restrict__ h,
       __nv_bfloat16* __restrict__ l, int n)
{
    const int i = blockIdx.x * blockDim.x + threadIdx.x;
    if (i >= n) return;
    const float v = src[i];
    const __nv_bfloat16 hv = __float2bfloat16_rn(v);
    h[i] = hv;
    l[i] = __float2bfloat16_rn(v - __bfloat162float(hv));
}

// x [B,N,D] fp32 -> xT hi/lo [B,D,N] bf16
__global__ void __launch_bounds__(256)
transpose_split(const float* __restrict__ src,
                __nv_bfloat16* __restrict__ th, __nv_bfloat16* __restrict__ tl)
{
    __shared__ float ts[32][33];
    const int z = blockIdx.z;
    const int d0 = blockIdx.x * 32, n0 = blockIdx.y * 32;
    const int tx = threadIdx.x & 31, ty = threadIdx.x >> 5;   // ty 0..7
    const float* s = src + ((size_t)z * Nn + n0) * Dd + d0;
    #pragma unroll
    for (int r = 0; r < 4; r++)
        ts[ty + r * 8][tx] = s[(size_t)(ty + r * 8) * Dd + tx];
    __syncthreads();
    __nv_bfloat16* ph = th + ((size_t)z * Dd + d0) * Nn + n0;
    __nv_bfloat16* pl = tl + ((size_t)z * Dd + d0) * Nn + n0;
    #pragma unroll
    for (int r = 0; r < 4; r++) {
        const float v = ts[tx][ty + r * 8];
        const __nv_bfloat16 h = __float2bfloat16_rn(v);
        ph[(size_t)(ty + r * 8) * Nn + tx] = h;
        pl[(size_t)(ty + r * 8) * Nn + tx] = __float2bfloat16_rn(v - __bfloat162float(h));
    }
}

// normalize one attn row (512) in place; also emit bf16 hi/lo
__global__ void __launch_bounds__(256)
rownorm_split(float* __restrict__ a, __nv_bfloat16* __restrict__ h,
              __nv_bfloat16* __restrict__ l)
{
    const size_t row = blockIdx.x;
    float* p = a + row * Nn;
    const int t = threadIdx.x;
    const float v0 = p[t];
    const float v1 = p[t + 256];
    float s = v0 + v1;
    #pragma unroll
    for (int o = 16; o; o >>= 1) s += __shfl_xor_sync(0xffffffffu, s, o);
    __shared__ float ws[8];
    if ((t & 31) == 0) ws[t >> 5] = s;
    __syncthreads();
    if (t < 8) {
        float x = ws[t];
        #pragma unroll
        for (int o = 4; o; o >>= 1) x += __shfl_xor_sync(0xffu, x, o);
        if (t == 0) ws[0] = x;
    }
    __syncthreads();
    const float inv = 1.0f / ws[0];
    const float n0 = v0 * inv, n1 = v1 * inv;
    p[t] = n0;
    p[t + 256] = n1;
    const __nv_bfloat16 h0 = __float2bfloat16_rn(n0);
    const __nv_bfloat16 h1 = __float2bfloat16_rn(n1);
    h[row * Nn + t] = h0;
    h[row * Nn + t + 256] = h1;
    l[row * Nn + t] = __float2bfloat16_rn(n0 - __bfloat162float(h0));
    l[row * Nn + t + 256] = __float2bfloat16_rn(n1 - __bfloat162float(h1));
}

// ======================= launch =======================
extern "C" void kernel_launch(void* const* d_in, const int* in_sizes, int n_in,
                              void* d_out, int out_size)
{
    const float* x_in  = (const float*)d_in[0];
    const float* adj   = (const float*)d_in[1];
    const float* wA_w  = (const float*)d_in[2];
    const float* wA_b  = (const float*)d_in[3];
    const float* l0_w  = (const float*)d_in[4];
    const float* l0_b  = (const float*)d_in[5];
    const float* l1_w  = (const float*)d_in[6];
    const float* l1_b  = (const float*)d_in[7];
    const float* fin_w = (const float*)d_in[8];
    const float* fin_b = (const float*)d_in[9];

    float* out_x = (float*)d_out;
    float* attls = out_x + (size_t)Bb * Nn * Dd;

    __nv_bfloat16 *xh, *xl, *th, *tl, *qh, *ql, *ah, *al, *wh, *wl;
    float* gx;
    cudaGetSymbolAddress((void**)&xh, g_xh); cudaGetSymbolAddress((void**)&xl, g_xl);
    cudaGetSymbolAddress((void**)&th, g_th); cudaGetSymbolAddress((void**)&tl, g_tl);
    cudaGetSymbolAddress((void**)&qh, g_qh); cudaGetSymbolAddress((void**)&ql, g_ql);
    cudaGetSymbolAddress((void**)&ah, g_ah); cudaGetSymbolAddress((void**)&al, g_al);
    cudaGetSymbolAddress((void**)&wh, g_wh); cudaGetSymbolAddress((void**)&wl, g_wl);
    cudaGetSymbolAddress((void**)&gx, g_x);

    cudaFuncSetAttribute(mma_gemm<1>, cudaFuncAttributeMaxDynamicSharedMemorySize, GEMM_SMEM);
    cudaFuncSetAttribute(mma_gemm<2>, cudaFuncAttributeMaxDynamicSharedMemorySize, GEMM_SMEM);
    cudaFuncSetAttribute(mma_gemm<3>, cudaFuncAttributeMaxDynamicSharedMemorySize, GEMM_SMEM);
    cudaFuncSetAttribute(mma_gemm<4>, cudaFuncAttributeMaxDynamicSharedMemorySize, GEMM_SMEM);
    cudaFuncSetAttribute(mma_gemm<5>, cudaFuncAttributeMaxDynamicSharedMemorySize, GEMM_SMEM);
    cudaFuncSetAttribute(mma_gemm<6>, cudaFuncAttributeMaxDynamicSharedMemorySize, GEMM_SMEM);

    const int WSZ = Dd * Dd;                 // 65536
    const long long sX = (long long)Nn * Dd; // per batch
    const long long sA = (long long)Nn * Nn; // per batch

    // split weights: [0..3]=wA, [4..7]=lin0, [8..11]=lin1, [12]=final
    wsplit<<<(4 * WSZ + 255) / 256, 256>>>(wA_w,  wh,            wl,            4 * WSZ);
    wsplit<<<(4 * WSZ + 255) / 256, 256>>>(l0_w,  wh + 4 * WSZ,  wl + 4 * WSZ,  4 * WSZ);
    wsplit<<<(4 * WSZ + 255) / 256, 256>>>(l1_w,  wh + 8 * WSZ,  wl + 8 * WSZ,  4 * WSZ);
    wsplit<<<(WSZ + 255) / 256, 256>>>(fin_w, wh + 12 * WSZ, wl + 12 * WSZ, WSZ);

    // x -> g_x (fp32) + xh/xl (bf16 split)
    {
        const int n4 = XSZ / 4;
        split_copy<<<(n4 + 255) / 256, 256>>>((const float4*)x_in, (float4*)gx, xh, xl, n4);
    }

    const int BIGM = Bb * Nn; // 32768
    for (int l = 0; l < Ll; l++) {
        const float* ba = wA_b + (size_t)l * Dd;
        const float* b0 = l0_b + (size_t)l * Dd;
        const float* b1 = l1_b + (size_t)l * Dd;
        const __nv_bfloat16* Wah = wh + (size_t)l * WSZ;
        const __nv_bfloat16* Wal = wl + (size_t)l * WSZ;
        const __nv_bfloat16* W0h = wh + (size_t)(4 + l) * WSZ;
        const __nv_bfloat16* W0l = wl + (size_t)(4 + l) * WSZ;
        const __nv_bfloat16* W1h = wh + (size_t)(8 + l) * WSZ;
        const __nv_bfloat16* W1l = wl + (size_t)(8 + l) * WSZ;
        float* attl = attls + (size_t)l * Bb * Nn * Nn;

        // xT hi/lo from g_x
        transpose_split<<<dim3(Dd / 32, Nn / 32, Bb), 256>>>(gx, th, tl);

        // q = x @ Wa^T + ba  ->  qh/ql
        mma_gemm<1><<<dim3(BIGM / TM, Dd / TN, 1), 256, GEMM_SMEM>>>(
            xh, xl, Wah, Wal, Dd, 0, 0,
            nullptr, qh, ql, 0, Dd, ba, nullptr, nullptr);

        // attn_unnorm = sig(q @ x^T)*adj (+diag)  -> attl (fp32)
        mma_gemm<2><<<dim3(Nn / TM, Nn / TN, Bb), 256, GEMM_SMEM>>>(
            qh, ql, xh, xl, Dd, sX, sX,
            attl, nullptr, nullptr, sA, Nn, nullptr, nullptr, adj);

        // normalize rows + split to ah/al
        rownorm_split<<<Bb * Nn, 256>>>(attl, ah, al);

        // t1 = attn @ x  (as NT with xT)  -> qh/ql
        mma_gemm<3><<<dim3(Nn / TM, Dd / TN, Bb), 256, GEMM_SMEM>>>(
            ah, al, th, tl, Nn, sA, sX,
            nullptr, qh, ql, sX, Dd, nullptr, nullptr, nullptr);

        // h = relu(t1 @ W0^T + b0) -> th/tl
        mma_gemm<4><<<dim3(BIGM / TM, Dd / TN, 1), 256, GEMM_SMEM>>>(
            qh, ql, W0h, W0l, Dd, 0, 0,
            nullptr, th, tl, 0, Dd, b0, nullptr, nullptr);

        // x = relu(h @ W1^T + b1) + x0 -> g_x (fp32) + xh/xl
        mma_gemm<5><<<dim3(BIGM / TM, Dd / TN, 1), 256, GEMM_SMEM>>>(
            th, tl, W1h, W1l, Dd, 0, 0,
            gx, xh, xl, 0, Dd, b1, gx, nullptr);
    }

    // out = x @ final^T + b
    mma_gemm<6><<<dim3(BIGM / TM, Dd / TN, 1), 256, GEMM_SMEM>>>(
        xh, xl, wh + 12 * WSZ, wl + 12 * WSZ, Dd, 0, 0,
        out_x, nullptr, nullptr, 0, Dd, fin_b, nullptr, nullptr);
}